// round 1
// baseline (speedup 1.0000x reference)
#include <cuda_runtime.h>

// LSTM_46316927320185
// B=4096, T=512, EMB=32, HID=16, VOCAB=50000. Output: sigmoid(h_T @ fc_w^T + fc_b), [B,1] fp32.
//
// Mapping: thread j (of 16 per batch element) owns hidden unit j; computes all
// 4 gates (i,f,g,o) for unit j each timestep. h exchanged via half-warp shfl.
// Weights staged in smem transposed + gate-packed float4 -> conflict-free LDS.128.
// One 448-thread CTA (28 elems) per SM, grid 147 -> balanced single wave.
// Embedding row for t+1 prefetched into registers during step t.

#define HID    16
#define EMB    32
#define T_LEN  512
#define BATCH  4096

#define ELEMS_PER_CTA 28
#define CTA_THREADS   (ELEMS_PER_CTA * HID)   // 448
#define GRID_CTAS     ((BATCH + ELEMS_PER_CTA - 1) / ELEMS_PER_CTA)  // 147

__device__ __forceinline__ float sigmoidf_fast(float x) {
    return __fdividef(1.0f, 1.0f + __expf(-x));
}
__device__ __forceinline__ float tanhf_fast(float x) {
    // tanh(x) = 2/(1+exp(-2x)) - 1 ; saturates correctly for |x| large.
    return __fdividef(2.0f, 1.0f + __expf(-2.0f * x)) - 1.0f;
}

__global__ __launch_bounds__(CTA_THREADS, 1)
void lstm_fused_kernel(const int*   __restrict__ x,
                       const float* __restrict__ embed,
                       const float* __restrict__ w_ih,
                       const float* __restrict__ w_hh,
                       const float* __restrict__ b_ih,
                       const float* __restrict__ b_hh,
                       const float* __restrict__ fc_w,
                       const float* __restrict__ fc_b,
                       float*       __restrict__ out)
{
    // [k][j] -> float4 of gate weights (i,f,g,o) for hidden unit j, input k
    __shared__ float4 w_ih4[EMB * HID];   // 8 KB
    __shared__ float4 w_hh4[HID * HID];   // 4 KB
    __shared__ float4 bias4[HID];
    __shared__ float4 emb_s4[ELEMS_PER_CTA * (EMB / 4)];  // 28 * 8 float4

    const int tid = threadIdx.x;

    // ---- stage weights (transpose + gate-pack) ----
    for (int i = tid; i < EMB * HID; i += CTA_THREADS) {
        int k = i / HID, j = i % HID;
        w_ih4[i] = make_float4(w_ih[(0 * HID + j) * EMB + k],
                               w_ih[(1 * HID + j) * EMB + k],
                               w_ih[(2 * HID + j) * EMB + k],
                               w_ih[(3 * HID + j) * EMB + k]);
    }
    for (int i = tid; i < HID * HID; i += CTA_THREADS) {
        int k = i / HID, j = i % HID;
        w_hh4[i] = make_float4(w_hh[(0 * HID + j) * HID + k],
                               w_hh[(1 * HID + j) * HID + k],
                               w_hh[(2 * HID + j) * HID + k],
                               w_hh[(3 * HID + j) * HID + k]);
    }
    if (tid < HID) {
        int j = tid;
        bias4[j] = make_float4(b_ih[0 * HID + j] + b_hh[0 * HID + j],
                               b_ih[1 * HID + j] + b_hh[1 * HID + j],
                               b_ih[2 * HID + j] + b_hh[2 * HID + j],
                               b_ih[3 * HID + j] + b_hh[3 * HID + j]);
    }
    __syncthreads();

    const int e = tid / HID;              // element slot within CTA
    const int j = tid % HID;              // hidden unit owned by this thread
    const int b = blockIdx.x * ELEMS_PER_CTA + e;
    const int bc = (b < BATCH) ? b : (BATCH - 1);   // clamp (dummy lanes compute, don't write)
    const int* __restrict__ xrow = x + (long)bc * T_LEN;

    const unsigned lane = tid & 31u;
    const unsigned halfbase = lane & 16u;  // shfl source base for this elem's half-warp

    float h = 0.0f, c = 0.0f;
    const float4 bias = bias4[j];

    float4* es4 = emb_s4 + e * (EMB / 4);

    // prefetch embedding row for t=0 (8 lanes of each half carry a float4)
    float4 pre = make_float4(0.f, 0.f, 0.f, 0.f);
    {
        int idx0 = xrow[0];
        if (j < 8) pre = ((const float4*)(embed + (long)idx0 * EMB))[j];
    }

    for (int t = 0; t < T_LEN; ++t) {
        __syncwarp();                      // prior step's emb reads complete
        if (j < 8) es4[j] = pre;
        __syncwarp();                      // emb visible to the half-warp

        // prefetch next timestep's embedding row (hides L2 gather latency)
        if (t + 1 < T_LEN) {
            int idxn = xrow[t + 1];
            if (j < 8) pre = ((const float4*)(embed + (long)idxn * EMB))[j];
        }

        float a0 = bias.x, a1 = bias.y, a2 = bias.z, a3 = bias.w;

        // input projection: 32 x (4 gates)
        #pragma unroll
        for (int kk = 0; kk < EMB / 4; ++kk) {
            const float4 ev = es4[kk];
            float4 w;
            w = w_ih4[(kk * 4 + 0) * HID + j];
            a0 = fmaf(ev.x, w.x, a0); a1 = fmaf(ev.x, w.y, a1);
            a2 = fmaf(ev.x, w.z, a2); a3 = fmaf(ev.x, w.w, a3);
            w = w_ih4[(kk * 4 + 1) * HID + j];
            a0 = fmaf(ev.y, w.x, a0); a1 = fmaf(ev.y, w.y, a1);
            a2 = fmaf(ev.y, w.z, a2); a3 = fmaf(ev.y, w.w, a3);
            w = w_ih4[(kk * 4 + 2) * HID + j];
            a0 = fmaf(ev.z, w.x, a0); a1 = fmaf(ev.z, w.y, a1);
            a2 = fmaf(ev.z, w.z, a2); a3 = fmaf(ev.z, w.w, a3);
            w = w_ih4[(kk * 4 + 3) * HID + j];
            a0 = fmaf(ev.w, w.x, a0); a1 = fmaf(ev.w, w.y, a1);
            a2 = fmaf(ev.w, w.z, a2); a3 = fmaf(ev.w, w.w, a3);
        }

        // recurrent projection: 16 x (4 gates); h broadcast via half-warp shfl
        #pragma unroll
        for (int k = 0; k < HID; ++k) {
            const float hv = __shfl_sync(0xffffffffu, h, halfbase + k);
            const float4 w = w_hh4[k * HID + j];
            a0 = fmaf(hv, w.x, a0); a1 = fmaf(hv, w.y, a1);
            a2 = fmaf(hv, w.z, a2); a3 = fmaf(hv, w.w, a3);
        }

        const float ig = sigmoidf_fast(a0);
        const float fg = sigmoidf_fast(a1);
        const float gg = tanhf_fast(a2);
        const float og = sigmoidf_fast(a3);
        c = fg * c + ig * gg;
        h = og * tanhf_fast(c);
    }

    // FC head: out[b] = sigmoid(sum_j h_j * fc_w[j] + fc_b)
    float v = h * fc_w[j];
    v += __shfl_xor_sync(0xffffffffu, v, 8);
    v += __shfl_xor_sync(0xffffffffu, v, 4);
    v += __shfl_xor_sync(0xffffffffu, v, 2);
    v += __shfl_xor_sync(0xffffffffu, v, 1);
    if (j == 0 && b < BATCH) out[b] = sigmoidf_fast(v + fc_b[0]);
}

extern "C" void kernel_launch(void* const* d_in, const int* in_sizes, int n_in,
                              void* d_out, int out_size)
{
    const int*   x     = (const int*)  d_in[0];
    const float* embed = (const float*)d_in[1];
    const float* w_ih  = (const float*)d_in[2];
    const float* w_hh  = (const float*)d_in[3];
    const float* b_ih  = (const float*)d_in[4];
    const float* b_hh  = (const float*)d_in[5];
    const float* fc_w  = (const float*)d_in[6];
    const float* fc_b  = (const float*)d_in[7];
    float* out = (float*)d_out;

    lstm_fused_kernel<<<GRID_CTAS, CTA_THREADS>>>(
        x, embed, w_ih, w_hh, b_ih, b_hh, fc_w, fc_b, out);
}

// round 3
// speedup vs baseline: 1.6562x; 1.6562x over previous
#include <cuda_runtime.h>

// LSTM_46316927320185 — R3 (R2 design + SMSP fix)
// B=4096, T=512, EMB=32, HID=16. out = sigmoid(h_T @ fc_w^T + fc_b), [B,1] fp32.
//
// R1 was smem-crossbar bound (L1 95.7%): 48 weight LDS.128 per elem per step.
// This version:
//  (a) 4 batch elements per thread -> weight LDS amortized 4x;
//  (b) fma.rn.f32x2 packed over the gate dimension -> FMA issue halved
//      (gate-pair weights come free as 64-bit halves of the float4 LDS.128);
//  (c) h exchange via smem (scalar STS + broadcast LDS.128) instead of shfl;
//  (d) CTA = 128 threads (4 warps -> all 4 SMSPs; wid%4 SMSP mapping makes
//      64-thread CTAs use only half the SM's schedulers/FMA pipes).
// CTA = 8 groups x 16 threads = 32 elems; grid 128 (single balanced wave).

#define HID    16
#define EMB    32
#define T_LEN  512
#define BATCH  4096

#define ELEMS_PER_CTA 32
#define CTA_THREADS   128
#define GRID_CTAS     (BATCH / ELEMS_PER_CTA)   // 128

typedef unsigned long long u64;

__device__ __forceinline__ u64 rep2(float v) {
    u64 r; asm("mov.b64 %0, {%1, %1};" : "=l"(r) : "f"(v)); return r;
}
__device__ __forceinline__ u64 pack2(float a, float b) {
    u64 r; asm("mov.b64 %0, {%1, %2};" : "=l"(r) : "f"(a), "f"(b)); return r;
}
__device__ __forceinline__ u64 fma2(u64 a, u64 b, u64 c) {
    u64 d; asm("fma.rn.f32x2 %0, %1, %2, %3;" : "=l"(d) : "l"(a), "l"(b), "l"(c)); return d;
}
__device__ __forceinline__ void unpack2(u64 v, float& lo, float& hi) {
    asm("mov.b64 {%0, %1}, %2;" : "=f"(lo), "=f"(hi) : "l"(v));
}

__device__ __forceinline__ float sigf(float x) {
    return __fdividef(1.0f, 1.0f + __expf(-x));
}
__device__ __forceinline__ float tanhf_fast(float x) {
    return __fdividef(2.0f, 1.0f + __expf(-2.0f * x)) - 1.0f;
}

__global__ __launch_bounds__(CTA_THREADS)
void lstm4_kernel(const int*   __restrict__ x,
                  const float* __restrict__ embed,
                  const float* __restrict__ w_ih,
                  const float* __restrict__ w_hh,
                  const float* __restrict__ b_ih,
                  const float* __restrict__ b_hh,
                  const float* __restrict__ fc_w,
                  const float* __restrict__ fc_b,
                  float*       __restrict__ out)
{
    // gate-packed transposed weights: entry [k*HID+j] = float4 (wi,wf,wg,wo),
    // viewed as ulonglong2 = { (wi,wf), (wg,wo) } packed f32x2 operands.
    __shared__ ulonglong2 w_ih_u[EMB * HID];   // 8 KB
    __shared__ ulonglong2 w_hh_u[HID * HID];   // 4 KB
    __shared__ float4 emb_s[ELEMS_PER_CTA * (EMB / 4)];  // 4 KB
    __shared__ float  h_s[ELEMS_PER_CTA * HID];          // 2 KB

    const int tid = threadIdx.x;

    for (int i = tid; i < EMB * HID; i += CTA_THREADS) {
        int k = i / HID, jj = i % HID;
        float4 w = make_float4(w_ih[(0 * HID + jj) * EMB + k],
                               w_ih[(1 * HID + jj) * EMB + k],
                               w_ih[(2 * HID + jj) * EMB + k],
                               w_ih[(3 * HID + jj) * EMB + k]);
        *(float4*)&w_ih_u[i] = w;
    }
    for (int i = tid; i < HID * HID; i += CTA_THREADS) {
        int k = i / HID, jj = i % HID;
        float4 w = make_float4(w_hh[(0 * HID + jj) * HID + k],
                               w_hh[(1 * HID + jj) * HID + k],
                               w_hh[(2 * HID + jj) * HID + k],
                               w_hh[(3 * HID + jj) * HID + k]);
        *(float4*)&w_hh_u[i] = w;
    }

    const int g  = tid >> 4;        // group 0..7 (half-warp)
    const int j  = tid & 15;        // hidden unit owned by this thread
    const int e0 = g * 4;           // local element base (4 elems per group)
    const int b0 = blockIdx.x * ELEMS_PER_CTA + e0;
    const int r  = j >> 2;          // which of the group's 4 elems this thread prefetches
    const int p  = j & 3;           // which float4 chunk of the emb row

    const u64 bias01 = pack2(b_ih[j]           + b_hh[j],
                             b_ih[HID + j]     + b_hh[HID + j]);
    const u64 bias23 = pack2(b_ih[2 * HID + j] + b_hh[2 * HID + j],
                             b_ih[3 * HID + j] + b_hh[3 * HID + j]);

    float h0 = 0.f, h1 = 0.f, h2 = 0.f, h3 = 0.f;
    float c0 = 0.f, c1 = 0.f, c2 = 0.f, c3 = 0.f;

    __syncthreads();   // weights staged

    const int* xcol = x + (long)(b0 + r) * T_LEN;
    float4 preA, preB;
    {
        int idx = xcol[0];
        const float4* row = (const float4*)(embed + (long)idx * EMB);
        preA = row[p]; preB = row[p + 4];
    }

    for (int t = 0; t < T_LEN; ++t) {
        __syncwarp();   // prior step's smem reads complete (groups are warp-local)
        emb_s[(e0 + r) * 8 + p]     = preA;
        emb_s[(e0 + r) * 8 + p + 4] = preB;
        h_s[(e0 + 0) * HID + j] = h0;
        h_s[(e0 + 1) * HID + j] = h1;
        h_s[(e0 + 2) * HID + j] = h2;
        h_s[(e0 + 3) * HID + j] = h3;
        __syncwarp();   // staging visible to group

        if (t + 1 < T_LEN) {
            int idx = xcol[t + 1];
            const float4* row = (const float4*)(embed + (long)idx * EMB);
            preA = row[p]; preB = row[p + 4];
        }

        u64 a01_0 = bias01, a23_0 = bias23;
        u64 a01_1 = bias01, a23_1 = bias23;
        u64 a01_2 = bias01, a23_2 = bias23;
        u64 a01_3 = bias01, a23_3 = bias23;

        // input projection: 32 k-values x 4 gates, packed over gate pairs
        #pragma unroll
        for (int kk = 0; kk < 8; ++kk) {
            const float4 ev0 = emb_s[(e0 + 0) * 8 + kk];
            const float4 ev1 = emb_s[(e0 + 1) * 8 + kk];
            const float4 ev2 = emb_s[(e0 + 2) * 8 + kk];
            const float4 ev3 = emb_s[(e0 + 3) * 8 + kk];
            #define IH_C(COMP, CI) { \
                const ulonglong2 wd = w_ih_u[(kk * 4 + CI) * HID + j]; \
                const u64 q0 = rep2(ev0.COMP), q1 = rep2(ev1.COMP); \
                const u64 q2 = rep2(ev2.COMP), q3 = rep2(ev3.COMP); \
                a01_0 = fma2(q0, wd.x, a01_0); a23_0 = fma2(q0, wd.y, a23_0); \
                a01_1 = fma2(q1, wd.x, a01_1); a23_1 = fma2(q1, wd.y, a23_1); \
                a01_2 = fma2(q2, wd.x, a01_2); a23_2 = fma2(q2, wd.y, a23_2); \
                a01_3 = fma2(q3, wd.x, a01_3); a23_3 = fma2(q3, wd.y, a23_3); }
            IH_C(x, 0) IH_C(y, 1) IH_C(z, 2) IH_C(w, 3)
            #undef IH_C
        }

        // recurrent projection: 16 k-values x 4 gates
        #pragma unroll
        for (int k4 = 0; k4 < 4; ++k4) {
            const float4 hv0 = *(const float4*)&h_s[(e0 + 0) * HID + k4 * 4];
            const float4 hv1 = *(const float4*)&h_s[(e0 + 1) * HID + k4 * 4];
            const float4 hv2 = *(const float4*)&h_s[(e0 + 2) * HID + k4 * 4];
            const float4 hv3 = *(const float4*)&h_s[(e0 + 3) * HID + k4 * 4];
            #define HH_C(COMP, CI) { \
                const ulonglong2 wd = w_hh_u[(k4 * 4 + CI) * HID + j]; \
                const u64 q0 = rep2(hv0.COMP), q1 = rep2(hv1.COMP); \
                const u64 q2 = rep2(hv2.COMP), q3 = rep2(hv3.COMP); \
                a01_0 = fma2(q0, wd.x, a01_0); a23_0 = fma2(q0, wd.y, a23_0); \
                a01_1 = fma2(q1, wd.x, a01_1); a23_1 = fma2(q1, wd.y, a23_1); \
                a01_2 = fma2(q2, wd.x, a01_2); a23_2 = fma2(q2, wd.y, a23_2); \
                a01_3 = fma2(q3, wd.x, a01_3); a23_3 = fma2(q3, wd.y, a23_3); }
            HH_C(x, 0) HH_C(y, 1) HH_C(z, 2) HH_C(w, 3)
            #undef HH_C
        }

        #define EPI(Q) { \
            float ai, af, ag, ao; \
            unpack2(a01_##Q, ai, af); unpack2(a23_##Q, ag, ao); \
            const float ig = sigf(ai), fg = sigf(af); \
            const float gg = tanhf_fast(ag), og = sigf(ao); \
            c##Q = fg * c##Q + ig * gg; \
            h##Q = og * tanhf_fast(c##Q); }
        EPI(0) EPI(1) EPI(2) EPI(3)
        #undef EPI
    }

    // FC head: per-element half-warp reduction over j
    const float fcw = fc_w[j];
    const float fcb = fc_b[0];
    #define RED(Q, HQ) { \
        float v = HQ * fcw; \
        v += __shfl_xor_sync(0xffffffffu, v, 8); \
        v += __shfl_xor_sync(0xffffffffu, v, 4); \
        v += __shfl_xor_sync(0xffffffffu, v, 2); \
        v += __shfl_xor_sync(0xffffffffu, v, 1); \
        if (j == 0) out[b0 + Q] = sigf(v + fcb); }
    RED(0, h0) RED(1, h1) RED(2, h2) RED(3, h3)
    #undef RED
}

extern "C" void kernel_launch(void* const* d_in, const int* in_sizes, int n_in,
                              void* d_out, int out_size)
{
    const int*   x     = (const int*)  d_in[0];
    const float* embed = (const float*)d_in[1];
    const float* w_ih  = (const float*)d_in[2];
    const float* w_hh  = (const float*)d_in[3];
    const float* b_ih  = (const float*)d_in[4];
    const float* b_hh  = (const float*)d_in[5];
    const float* fc_w  = (const float*)d_in[6];
    const float* fc_b  = (const float*)d_in[7];
    float* out = (float*)d_out;

    lstm4_kernel<<<GRID_CTAS, CTA_THREADS>>>(
        x, embed, w_ih, w_hh, b_ih, b_hh, fc_w, fc_b, out);
}

// round 4
// speedup vs baseline: 2.2525x; 1.3600x over previous
#include <cuda_runtime.h>

// LSTM_46316927320185 — R4: register-resident weights + 2 warps/SMSP
// B=4096, T=512, EMB=32, HID=16. out = sigmoid(h_T @ fc_w^T + fc_b), [B,1] fp32.
//
// R3 was latency-bound: 1 warp/SMSP (occ 6.2%) left ~2/3 of each step as
// exposed LDS/MUFU latency. Adding warps re-inflates weight LDS traffic, so:
//  - Weights live in REGISTERS (96 fp32/thread): lane (gp=lane>>4, j=lane&15)
//    owns unit j, all 4 gates, over HALF the K range (gp0: emb k0-15, h k0-7;
//    gp1: the rest). Zero weight LDS in the loop.
//  - Halves merged with one shfl_xor(16) + add.rn.f32x2 per accumulator.
//  - Epilogue computed redundantly in both halves (free in warp-instrs).
//  - CTA 256 = 8 warps -> 2 warps/SMSP for latency hiding; 4 elems/warp,
//    32 elems/CTA, grid 128, zero tail.
//  - emb prefetch: one full-width LDG.128/warp (lane -> elem x chunk).

#define HID    16
#define EMB    32
#define T_LEN  512
#define BATCH  4096

#define WARPS_PER_CTA 8
#define ELEMS_PER_CTA 32          // 4 per warp
#define CTA_THREADS   256
#define GRID_CTAS     (BATCH / ELEMS_PER_CTA)   // 128

typedef unsigned long long u64;

__device__ __forceinline__ u64 rep2(float v) {
    u64 r; asm("mov.b64 %0, {%1, %1};" : "=l"(r) : "f"(v)); return r;
}
__device__ __forceinline__ u64 pack2(float a, float b) {
    u64 r; asm("mov.b64 %0, {%1, %2};" : "=l"(r) : "f"(a), "f"(b)); return r;
}
__device__ __forceinline__ u64 fma2(u64 a, u64 b, u64 c) {
    u64 d; asm("fma.rn.f32x2 %0, %1, %2, %3;" : "=l"(d) : "l"(a), "l"(b), "l"(c)); return d;
}
__device__ __forceinline__ u64 add2(u64 a, u64 b) {
    u64 d; asm("add.rn.f32x2 %0, %1, %2;" : "=l"(d) : "l"(a), "l"(b)); return d;
}
__device__ __forceinline__ void unpack2(u64 v, float& lo, float& hi) {
    asm("mov.b64 {%0, %1}, %2;" : "=f"(lo), "=f"(hi) : "l"(v));
}

__device__ __forceinline__ float sigf(float x) {
    return __fdividef(1.0f, 1.0f + __expf(-x));
}
__device__ __forceinline__ float tanhf_fast(float x) {
    return __fdividef(2.0f, 1.0f + __expf(-2.0f * x)) - 1.0f;
}

__global__ __launch_bounds__(CTA_THREADS, 1)
void lstm_rw_kernel(const int*   __restrict__ x,
                    const float* __restrict__ embed,
                    const float* __restrict__ w_ih,
                    const float* __restrict__ w_hh,
                    const float* __restrict__ b_ih,
                    const float* __restrict__ b_hh,
                    const float* __restrict__ fc_w,
                    const float* __restrict__ fc_b,
                    float*       __restrict__ out)
{
    // transient weight staging (gate-packed, transposed): [k][j] -> (wi,wf),(wg,wo)
    __shared__ ulonglong2 w_ih_u[EMB * HID];          // 8 KB
    __shared__ ulonglong2 w_hh_u[HID * HID];          // 4 KB
    __shared__ float4     emb_s4[ELEMS_PER_CTA * 8];  // 16 KB: [elem][chunk0..7]
    __shared__ float      h_s[ELEMS_PER_CTA * HID];   // 2 KB:  [elem][j]

    const int tid = threadIdx.x;

    for (int i = tid; i < EMB * HID; i += CTA_THREADS) {
        int k = i / HID, jj = i % HID;
        float4 w = make_float4(w_ih[(0 * HID + jj) * EMB + k],
                               w_ih[(1 * HID + jj) * EMB + k],
                               w_ih[(2 * HID + jj) * EMB + k],
                               w_ih[(3 * HID + jj) * EMB + k]);
        *(float4*)&w_ih_u[i] = w;
    }
    for (int i = tid; i < HID * HID; i += CTA_THREADS) {
        int k = i / HID, jj = i % HID;
        float4 w = make_float4(w_hh[(0 * HID + jj) * HID + k],
                               w_hh[(1 * HID + jj) * HID + k],
                               w_hh[(2 * HID + jj) * HID + k],
                               w_hh[(3 * HID + jj) * HID + k]);
        *(float4*)&w_hh_u[i] = w;
    }
    __syncthreads();

    const int warp = tid >> 5;
    const int lane = tid & 31;
    const int j    = lane & 15;      // hidden unit owned
    const int gp   = lane >> 4;      // K-range half: 0 or 1
    const int we   = warp * 4;       // first local elem of this warp
    const int b0w  = blockIdx.x * ELEMS_PER_CTA + we;

    // ---- weights -> registers (this thread's half of K) ----
    u64 wih01[16], wih23[16];        // emb k = gp*16 + 0..15
    u64 whh01[8],  whh23[8];         // h   k = gp*8  + 0..7
    #pragma unroll
    for (int k = 0; k < 16; ++k) {
        ulonglong2 w = w_ih_u[(gp * 16 + k) * HID + j];
        wih01[k] = w.x; wih23[k] = w.y;
    }
    #pragma unroll
    for (int k = 0; k < 8; ++k) {
        ulonglong2 w = w_hh_u[(gp * 8 + k) * HID + j];
        whh01[k] = w.x; whh23[k] = w.y;
    }

    // bias added only in gp0 half (halves are summed later)
    const u64 bias01 = gp ? 0ull : pack2(b_ih[j]           + b_hh[j],
                                         b_ih[HID + j]     + b_hh[HID + j]);
    const u64 bias23 = gp ? 0ull : pack2(b_ih[2 * HID + j] + b_hh[2 * HID + j],
                                         b_ih[3 * HID + j] + b_hh[3 * HID + j]);

    float h[4] = {0.f, 0.f, 0.f, 0.f};
    float c[4] = {0.f, 0.f, 0.f, 0.f};

    // emb prefetch: lane covers elem (lane>>3), chunk (lane&7) -> full-width LDG.128
    const int pe    = lane >> 3;                 // 0..3
    const int chunk = lane & 7;                  // 0..7
    const int* xcol = x + (long)(b0w + pe) * T_LEN;

    float4 pre;
    {
        int idx = xcol[0];
        pre = ((const float4*)(embed + (long)idx * EMB))[chunk];
    }

    const float4* h_s4 = (const float4*)h_s;

    for (int t = 0; t < T_LEN; ++t) {
        __syncwarp();                                  // prior step's smem reads done
        emb_s4[(we + pe) * 8 + chunk] = pre;
        h_s[(we + gp * 2 + 0) * HID + j] = h[gp * 2 + 0];
        h_s[(we + gp * 2 + 1) * HID + j] = h[gp * 2 + 1];
        __syncwarp();                                  // staging visible

        if (t + 1 < T_LEN) {
            int idx = xcol[t + 1];
            pre = ((const float4*)(embed + (long)idx * EMB))[chunk];
        }

        u64 a01[4], a23[4];
        #pragma unroll
        for (int e = 0; e < 4; ++e) { a01[e] = bias01; a23[e] = bias23; }

        // input projection: this half's 16 emb values x 4 gates
        #pragma unroll
        for (int e = 0; e < 4; ++e) {
            #pragma unroll
            for (int c4 = 0; c4 < 4; ++c4) {
                const float4 ev = emb_s4[(we + e) * 8 + gp * 4 + c4];
                u64 q;
                q = rep2(ev.x);
                a01[e] = fma2(q, wih01[c4 * 4 + 0], a01[e]);
                a23[e] = fma2(q, wih23[c4 * 4 + 0], a23[e]);
                q = rep2(ev.y);
                a01[e] = fma2(q, wih01[c4 * 4 + 1], a01[e]);
                a23[e] = fma2(q, wih23[c4 * 4 + 1], a23[e]);
                q = rep2(ev.z);
                a01[e] = fma2(q, wih01[c4 * 4 + 2], a01[e]);
                a23[e] = fma2(q, wih23[c4 * 4 + 2], a23[e]);
                q = rep2(ev.w);
                a01[e] = fma2(q, wih01[c4 * 4 + 3], a01[e]);
                a23[e] = fma2(q, wih23[c4 * 4 + 3], a23[e]);
            }
        }

        // recurrent projection: this half's 8 h values x 4 gates
        #pragma unroll
        for (int e = 0; e < 4; ++e) {
            #pragma unroll
            for (int c2 = 0; c2 < 2; ++c2) {
                const float4 hv = h_s4[(we + e) * 4 + gp * 2 + c2];
                u64 q;
                q = rep2(hv.x);
                a01[e] = fma2(q, whh01[c2 * 4 + 0], a01[e]);
                a23[e] = fma2(q, whh23[c2 * 4 + 0], a23[e]);
                q = rep2(hv.y);
                a01[e] = fma2(q, whh01[c2 * 4 + 1], a01[e]);
                a23[e] = fma2(q, whh23[c2 * 4 + 1], a23[e]);
                q = rep2(hv.z);
                a01[e] = fma2(q, whh01[c2 * 4 + 2], a01[e]);
                a23[e] = fma2(q, whh23[c2 * 4 + 2], a23[e]);
                q = rep2(hv.w);
                a01[e] = fma2(q, whh01[c2 * 4 + 3], a01[e]);
                a23[e] = fma2(q, whh23[c2 * 4 + 3], a23[e]);
            }
        }

        // merge halves: both sides end with the full gate preactivations
        #pragma unroll
        for (int e = 0; e < 4; ++e) {
            a01[e] = add2(a01[e], __shfl_xor_sync(0xffffffffu, a01[e], 16));
            a23[e] = add2(a23[e], __shfl_xor_sync(0xffffffffu, a23[e], 16));
        }

        // epilogue (redundant across halves; free in warp-instr count)
        #pragma unroll
        for (int e = 0; e < 4; ++e) {
            float ai, af, ag, ao;
            unpack2(a01[e], ai, af);
            unpack2(a23[e], ag, ao);
            const float ig = sigf(ai), fg = sigf(af);
            const float gg = tanhf_fast(ag), og = sigf(ao);
            c[e] = fg * c[e] + ig * gg;
            h[e] = og * tanhf_fast(c[e]);
        }
    }

    // FC head: reduce over j within the half-warp (gp0 lane j==0 writes)
    const float fcw = fc_w[j];
    const float fcb = fc_b[0];
    #pragma unroll
    for (int e = 0; e < 4; ++e) {
        float v = h[e] * fcw;
        v += __shfl_xor_sync(0xffffffffu, v, 8);
        v += __shfl_xor_sync(0xffffffffu, v, 4);
        v += __shfl_xor_sync(0xffffffffu, v, 2);
        v += __shfl_xor_sync(0xffffffffu, v, 1);
        if (lane == 0) out[b0w + e] = sigf(v + fcb);
    }
}

extern "C" void kernel_launch(void* const* d_in, const int* in_sizes, int n_in,
                              void* d_out, int out_size)
{
    const int*   x     = (const int*)  d_in[0];
    const float* embed = (const float*)d_in[1];
    const float* w_ih  = (const float*)d_in[2];
    const float* w_hh  = (const float*)d_in[3];
    const float* b_ih  = (const float*)d_in[4];
    const float* b_hh  = (const float*)d_in[5];
    const float* fc_w  = (const float*)d_in[6];
    const float* fc_b  = (const float*)d_in[7];
    float* out = (float*)d_out;

    lstm_rw_kernel<<<GRID_CTAS, CTA_THREADS>>>(
        x, embed, w_ih, w_hh, b_ih, b_hh, fc_w, fc_b, out);
}